// round 3
// baseline (speedup 1.0000x reference)
#include <cuda_runtime.h>

// LSTM_21869973471591 — B=4096, T=200, IN=2, H=64 (gates 4H=256)
//
// R3: operand-residency swap. R2 was shared-pipe bound (L1=88.6%) because
// W_hh lived in registers and h was fetched via broadcast LDS.128 (16 useful
// bytes per wavefront, 1 LDS : 2 FFMA2). Now:
//   - W_hh streams from smem, transposed+gate-interleaved: Wt4[k][n] =
//     {W_i[n][k], W_f[n][k], W_g[n][k], W_o[n][k]} -> one coalesced LDS.128
//     per (warp,k) yields both packed fma2 operands {wi,wf},{wg,wo}.
//   - h stored PRE-DUPLICATED as {h,h} float2 -> LDS.64 broadcast is directly
//     an fma2 operand; no packing movs in the inner loop.
//   - thread owns hidden unit n for 7 batch rows: all 4 gate types in
//     registers -> activation fully in-register, c in registers, no g_s
//     smem round trip, ONE __syncthreads per step, hd double-buffered.
// 128-thread CTAs, NB=14 rows, grid=293 -> 2 CTAs on every SM (balanced).

#define B_TOT  4096
#define T_LEN  200
#define H_DIM  64
#define NB     14
#define RM     7            // rows per thread (2 row-groups of 7)
#define CH     20           // x staging chunk (200 % 20 == 0)
#define NTH    128
#define GRID   293          // ceil(4096/14)

// dynamic smem layout (bytes)
#define OFF_W   0
#define SZ_W    (64 * 64 * 16)          // Wt4[k][n] float4       = 65536
#define OFF_HD  (OFF_W + SZ_W)
#define SZ_HD   (2 * NB * 64 * 8)       // hd[2][NB][64] float2   = 14336
#define OFF_XD  (OFF_HD + SZ_HD)
#define SZ_XD   (NB * CH * 16)          // xd[NB][CH] float4      = 4480
#define SMEM_TOTAL (OFF_XD + SZ_XD)     // 84352 B -> 2 CTAs/SM

typedef unsigned long long u64;

__device__ __forceinline__ u64 pack2(float lo, float hi) {
    u64 r; asm("mov.b64 %0, {%1, %2};" : "=l"(r) : "f"(lo), "f"(hi)); return r;
}
__device__ __forceinline__ void unpack2(u64 v, float& lo, float& hi) {
    asm("mov.b64 {%0, %1}, %2;" : "=f"(lo), "=f"(hi) : "l"(v));
}
__device__ __forceinline__ void fma2(u64& acc, u64 a, u64 b) {
    asm("fma.rn.f32x2 %0, %1, %2, %0;" : "+l"(acc) : "l"(a), "l"(b));
}
__device__ __forceinline__ float fast_rcp(float x) {
    float r; asm("rcp.approx.f32 %0, %1;" : "=f"(r) : "f"(x)); return r;
}
__device__ __forceinline__ float fast_ex2(float x) {
    float r; asm("ex2.approx.f32 %0, %1;" : "=f"(r) : "f"(x)); return r;
}
// accurate sigmoid/tanh via ex2.approx (~2^-22) + rcp.approx (validated
// rel_err 3e-7 in R1/R2); tanh.approx (2^-10) would risk the 1e-3 bound.
__device__ __forceinline__ float sigmoid_f(float x) {
    float e = fast_ex2(-1.4426950408889634f * x);
    return fast_rcp(1.0f + e);
}
__device__ __forceinline__ float tanh_f(float x) {
    float e = fast_ex2(2.8853900817779268f * x);
    return fmaf(-2.0f, fast_rcp(1.0f + e), 1.0f);
}

__global__ __launch_bounds__(NTH)
void lstm_kernel(const float* __restrict__ x,      // [B, T, 2]
                 const float* __restrict__ W_ih,   // [256, 2]
                 const float* __restrict__ W_hh,   // [256, 64]
                 const float* __restrict__ b_ih,   // [256]
                 const float* __restrict__ b_hh,   // [256]
                 const float* __restrict__ W_fc,   // [1, 64]
                 const float* __restrict__ b_fc,   // [1]
                 float* __restrict__ out)          // [B, 1]
{
    extern __shared__ char smem[];
    float*           wt_f  = (float*)(smem + OFF_W);
    const ulonglong2* wt2  = (const ulonglong2*)(smem + OFF_W);   // [k*64 + n]
    u64*             hd    = (u64*)(smem + OFF_HD);               // [(buf*NB+rb)*64 + k] = {h,h}
    float4*          xd    = (float4*)(smem + OFF_XD);            // [b*CH + tc] = {x0,x0,x1,x1}

    const int tid  = threadIdx.x;
    const int rg   = tid >> 6;          // row-group 0/1
    const int n    = tid & 63;          // hidden unit owned by this thread
    const int row0 = blockIdx.x * NB;

    // per-unit W_ih / bias, packed for fma2 (one-time)
    const u64 wx0_if = pack2(W_ih[(n)*2 + 0],       W_ih[(64 + n)*2 + 0]);
    const u64 wx1_if = pack2(W_ih[(n)*2 + 1],       W_ih[(64 + n)*2 + 1]);
    const u64 wx0_go = pack2(W_ih[(128 + n)*2 + 0], W_ih[(192 + n)*2 + 0]);
    const u64 wx1_go = pack2(W_ih[(128 + n)*2 + 1], W_ih[(192 + n)*2 + 1]);
    const u64 bias_if = pack2(b_ih[n] + b_hh[n],           b_ih[64 + n] + b_hh[64 + n]);
    const u64 bias_go = pack2(b_ih[128 + n] + b_hh[128 + n], b_ih[192 + n] + b_hh[192 + n]);

    // transpose W_hh into gate-interleaved Wt4[k][n] = {Wi,Wf,Wg,Wo}[n][k]
    // (rg splits the 4 gate types 2/2; STS addresses are conflict-free per type)
    for (int tt = rg; tt < 4; tt += 2) {
        const float4* wrow = (const float4*)(W_hh + (tt * 64 + n) * 64);
        #pragma unroll
        for (int k4 = 0; k4 < 16; k4++) {
            float4 v = wrow[k4];
            wt_f[((4*k4 + 0) * 64 + n) * 4 + tt] = v.x;
            wt_f[((4*k4 + 1) * 64 + n) * 4 + tt] = v.y;
            wt_f[((4*k4 + 2) * 64 + n) * 4 + tt] = v.z;
            wt_f[((4*k4 + 3) * 64 + n) * 4 + tt] = v.w;
        }
    }
    // h = 0 (both buffers)
    for (int i = tid; i < 2 * NB * 64; i += NTH) hd[i] = 0ull;

    float c[RM];
    #pragma unroll
    for (int b = 0; b < RM; b++) c[b] = 0.0f;

    __syncthreads();

    for (int t = 0; t < T_LEN; t++) {
        const int tc = t % CH;
        if (tc == 0) {
            // stage x[t..t+CH) duplicated: xd = {x0,x0,x1,x1}
            for (int idx = tid; idx < NB * CH; idx += NTH) {
                int b = idx / CH, cc = idx - b * CH;
                int row = row0 + b; if (row > B_TOT - 1) row = B_TOT - 1;
                float2 xv = *(const float2*)(x + (row * T_LEN + t + cc) * 2);
                xd[b * CH + cc] = make_float4(xv.x, xv.x, xv.y, xv.y);
            }
            __syncthreads();
        }

        const int p = t & 1;                     // read buffer
        const u64* hrd = hd + (p * NB + rg * RM) * 64;

        // ---- gate phase: acc[{i,f}] and acc[{g,o}] for 7 rows ----
        u64 aif[RM], ago[RM];
        #pragma unroll
        for (int b = 0; b < RM; b++) {
            ulonglong2 xq = *(const ulonglong2*)&xd[(rg * RM + b) * CH + tc];
            u64 a0 = bias_if; fma2(a0, wx0_if, xq.x); fma2(a0, wx1_if, xq.y);
            u64 a1 = bias_go; fma2(a1, wx0_go, xq.x); fma2(a1, wx1_go, xq.y);
            aif[b] = a0; ago[b] = a1;
        }
        #pragma unroll 8
        for (int k = 0; k < H_DIM; k++) {
            ulonglong2 w4 = wt2[k * 64 + n];     // {wi,wf},{wg,wo} coalesced
            #pragma unroll
            for (int b = 0; b < RM; b++) {
                u64 hv = hrd[b * 64 + k];        // {h,h} broadcast
                fma2(aif[b], w4.x, hv);
                fma2(ago[b], w4.y, hv);
            }
        }

        // ---- activation, fully in-register; write h for step t+1 ----
        u64* hwr = hd + ((1 - p) * NB + rg * RM) * 64;
        #pragma unroll
        for (int b = 0; b < RM; b++) {
            float gi, gf, gg, go_;
            unpack2(aif[b], gi, gf);
            unpack2(ago[b], gg, go_);
            float iv = sigmoid_f(gi);
            float fv = sigmoid_f(gf);
            float ov = sigmoid_f(go_);
            float gv = tanh_f(gg);
            float cv = fmaf(fv, c[b], iv * gv);
            c[b] = cv;
            float h = ov * tanh_f(cv);
            hwr[b * 64 + n] = pack2(h, h);
        }
        __syncthreads();
    }

    // final h is in buffer 0 (t=199 writes 1-(199&1) = 0)
    if (tid < NB) {
        int row = row0 + tid;
        if (row < B_TOT) {
            float s = b_fc[0];
            const u64* hrow = hd + (0 * NB + tid) * 64;
            #pragma unroll
            for (int k = 0; k < H_DIM; k++) {
                float lo, hi; unpack2(hrow[k], lo, hi); (void)hi;
                s = fmaf(lo, W_fc[k], s);
            }
            out[row] = s;
        }
    }
}

extern "C" void kernel_launch(void* const* d_in, const int* in_sizes, int n_in,
                              void* d_out, int out_size) {
    const float* x    = (const float*)d_in[0];
    const float* W_ih = (const float*)d_in[1];
    const float* W_hh = (const float*)d_in[2];
    const float* b_ih = (const float*)d_in[3];
    const float* b_hh = (const float*)d_in[4];
    const float* W_fc = (const float*)d_in[5];
    const float* b_fc = (const float*)d_in[6];
    float* out = (float*)d_out;
    (void)in_sizes; (void)n_in; (void)out_size;

    static int attr_set = 0;
    if (!attr_set) {
        cudaFuncSetAttribute(lstm_kernel,
                             cudaFuncAttributeMaxDynamicSharedMemorySize,
                             SMEM_TOTAL);
        attr_set = 1;
    }
    lstm_kernel<<<GRID, NTH, SMEM_TOTAL>>>(x, W_ih, W_hh, b_ih, b_hh,
                                           W_fc, b_fc, out);
}